// round 7
// baseline (speedup 1.0000x reference)
#include <cuda_runtime.h>
#include <float.h>

// Density_loss: mean-of-16-NN squared distances per point, averaged per cloud,
// MSE between seed and gt over batch. B=8, N=2048, C=3, K=16.
//
// ALU-pipe-bound analysis: the 16-slot FMNMX insert chain dominates. This
// version uses expansion-form distances (3 FFMA + 1 FADD via precomputed
// {-2x,-2y,-2z,|p|^2}), a warp-uniform vote event gate, and a two-level
// chain (upper-8 always, lower-8 only when some lane needs it).

#define NPTS  2048
#define BLK   256
#define TILES (NPTS / BLK)   // 8
#define BATCH 8
#define KNN   16

__device__ float g_partials[2 * BATCH * TILES];

__global__ __launch_bounds__(BLK, 1)
void knn_tile_kernel(const float* __restrict__ seed,
                     const float* __restrict__ gt) {
    __shared__ float4 sp[NPTS];          // {-2x, -2y, -2z, |p|^2}  (32 KB)
    __shared__ float  sred[BLK / 32];

    const int tile  = blockIdx.x;
    const int b     = blockIdx.y;
    const int which = blockIdx.z;

    const float* __restrict__ pts =
        (which == 0 ? seed : gt) + (size_t)b * NPTS * 3;

    // Stage transformed points: d(q,p) = |q|^2 + |p|^2 - 2 q.p
    //                                  = fma(-2px,qx, fma(-2py,qy, fma(-2pz,qz, |q|^2+|p|^2)))
    for (int i = threadIdx.x; i < NPTS; i += BLK) {
        const float x = pts[3 * i + 0];
        const float y = pts[3 * i + 1];
        const float z = pts[3 * i + 2];
        sp[i] = make_float4(-2.0f * x, -2.0f * y, -2.0f * z,
                            fmaf(x, x, fmaf(y, y, z * z)));
    }
    __syncthreads();

    const int qi = tile * BLK + threadIdx.x;
    const float4 q = sp[qi];
    const float qx  = -0.5f * q.x;
    const float qy  = -0.5f * q.y;
    const float qz  = -0.5f * q.z;
    const float qsq = q.w;

    // Sorted ascending top-16 (registers; all indices compile-time constants).
    float best[KNN];
#pragma unroll
    for (int k = 0; k < KNN; ++k) best[k] = FLT_MAX;
    float thresh = FLT_MAX;   // == best[15]
    float mid    = FLT_MAX;   // == best[7]

#pragma unroll 2
    for (int j0 = 0; j0 < NPTS; j0 += 4) {
        // Batch the 4 shared loads + distance math first (MLP + fma-pipe ILP).
        const float4 p0 = sp[j0 + 0];
        const float4 p1 = sp[j0 + 1];
        const float4 p2 = sp[j0 + 2];
        const float4 p3 = sp[j0 + 3];
        float d[4];
        d[0] = fmaf(p0.x, qx, fmaf(p0.y, qy, fmaf(p0.z, qz, qsq + p0.w)));
        d[1] = fmaf(p1.x, qx, fmaf(p1.y, qy, fmaf(p1.z, qz, qsq + p1.w)));
        d[2] = fmaf(p2.x, qx, fmaf(p2.y, qy, fmaf(p2.z, qz, qsq + p2.w)));
        d[3] = fmaf(p3.x, qx, fmaf(p3.y, qy, fmaf(p3.z, qz, qsq + p3.w)));

#pragma unroll
        for (int u = 0; u < 4; ++u) {
            const float dv = d[u];
            // Warp-uniform event gate: skip everything when no lane improves.
            if (__any_sync(0xffffffffu, dv < thresh)) {
                // Branchless per-lane: FLT_MAX falls off the end harmlessly.
                float v = (dv < thresh) ? dv : FLT_MAX;
                if (__any_sync(0xffffffffu, v < mid)) {
                    // Some lane inserts into the lower half: full 16-chain.
#pragma unroll
                    for (int k = 0; k < KNN; ++k) {
                        const float lo = fminf(best[k], v);
                        v       = fmaxf(best[k], v);
                        best[k] = lo;
                    }
                } else {
                    // All inserting lanes land in slots 8..15: half chain.
#pragma unroll
                    for (int k = KNN / 2; k < KNN; ++k) {
                        const float lo = fminf(best[k], v);
                        v       = fmaxf(best[k], v);
                        best[k] = lo;
                    }
                }
                mid    = best[KNN / 2 - 1];
                thresh = best[KNN - 1];
            }
        }
    }

    // Mean of the 16 nearest squared distances for this query.
    float s = 0.0f;
#pragma unroll
    for (int k = 0; k < KNN; ++k) s += best[k];
    s *= (1.0f / KNN);

    // Deterministic block reduction.
#pragma unroll
    for (int off = 16; off > 0; off >>= 1)
        s += __shfl_down_sync(0xffffffffu, s, off);
    if ((threadIdx.x & 31) == 0) sred[threadIdx.x >> 5] = s;
    __syncthreads();
    if (threadIdx.x == 0) {
        float t = 0.0f;
#pragma unroll
        for (int w = 0; w < BLK / 32; ++w) t += sred[w];
        g_partials[(which * BATCH + b) * TILES + tile] = t;
    }
}

__global__ void finalize_kernel(float* __restrict__ out) {
    const int lane = threadIdx.x;   // launched with 32 threads
    float s = 0.0f;
    if (lane < 2 * BATCH) {
        const int base = lane * TILES;     // lane = which*8 + b
#pragma unroll
        for (int t = 0; t < TILES; ++t) s += g_partials[base + t];
        s *= (1.0f / NPTS);
    }
    const float other = __shfl_xor_sync(0xffffffffu, s, 8); // pair seed<->gt
    float diff = s - other;
    float d2   = diff * diff;
    if (lane >= 8) d2 = 0.0f;
#pragma unroll
    for (int off = 4; off > 0; off >>= 1)
        d2 += __shfl_down_sync(0xffffffffu, d2, off);
    if (lane == 0) out[0] = d2 * (1.0f / BATCH);
}

extern "C" void kernel_launch(void* const* d_in, const int* in_sizes, int n_in,
                              void* d_out, int out_size) {
    const float* seed = (const float*)d_in[0];
    const float* gt_s = (const float*)d_in[1];
    float* out = (float*)d_out;

    dim3 grid(TILES, BATCH, 2);
    knn_tile_kernel<<<grid, BLK>>>(seed, gt_s);
    finalize_kernel<<<1, 32>>>(out);
}